// round 9
// baseline (speedup 1.0000x reference)
#include <cuda_runtime.h>
#include <cuda_fp16.h>
#include <cstdint>

// LNN Euler-Lagrange residual: ReLU MLP => grad-of-grad vanishes under
// autodiff; output is exactly -dL/dq.
//
// mma.sync.m16n8k16 chain (4 GEMMs, register-only glue; C-frag layout ==
// A-frag layout so each GEMM's output feeds the next GEMM's A operand
// without smem). fp16 hi/lo split, 3 products per MAC tile (~2^-21 err).
//
// R9 vs R8: 256-thread blocks at 2 CTAs/SM -> 16 warps/SM (4 per SMSP,
// was 3) under a 128-reg cap, and ldmatrix batched in groups of 8 ahead
// of their MMAs (MLP=8 instead of lockstep load->use). Accumulation order
// per c[nt] unchanged -> numerics identical to R7/R8.

typedef uint32_t u32;

__device__ __forceinline__ u32 smem_addr(const void* p) {
    u32 a;
    asm("{ .reg .u64 t; cvta.to.shared.u64 t, %1; cvt.u32.u64 %0, t; }"
        : "=r"(a) : "l"(p));
    return a;
}
__device__ __forceinline__ u32 pack_f16x2(float x0, float x1) {   // lo=x0, hi=x1
    u32 r; asm("cvt.rn.f16x2.f32 %0, %1, %2;" : "=r"(r) : "f"(x1), "f"(x0));
    return r;
}
__device__ __forceinline__ float2 unpack_h2(u32 v) {
    float2 r;
    asm("{ .reg .b16 lo1, hi1; mov.b32 {lo1, hi1}, %2; "
        "cvt.f32.f16 %0, lo1; cvt.f32.f16 %1, hi1; }"
        : "=f"(r.x), "=f"(r.y) : "r"(v));
    return r;
}
__device__ __forceinline__ void split2(float x0, float x1, u32& hi, u32& lo) {
    hi = pack_f16x2(x0, x1);
    const float2 hf = unpack_h2(hi);
    lo = pack_f16x2(x0 - hf.x, x1 - hf.y);
}
__device__ __forceinline__ void ldm4(u32 r[4], u32 addr) {
    asm volatile("ldmatrix.sync.aligned.m8n8.x4.shared.b16 {%0,%1,%2,%3}, [%4];"
                 : "=r"(r[0]), "=r"(r[1]), "=r"(r[2]), "=r"(r[3]) : "r"(addr));
}
#define MMA(cc, aa, b0, b1)                                                  \
    asm volatile("mma.sync.aligned.m16n8k16.row.col.f32.f16.f16.f32 "        \
        "{%0,%1,%2,%3}, {%4,%5,%6,%7}, {%8,%9}, {%0,%1,%2,%3};"              \
        : "+f"((cc)[0]), "+f"((cc)[1]), "+f"((cc)[2]), "+f"((cc)[3])         \
        : "r"((aa)[0]), "r"((aa)[1]), "r"((aa)[2]), "r"((aa)[3]),            \
          "r"(b0), "r"(b1))

// smem: weight tiles [n][k] fp16, row stride 72 halfs (144 B -> ldmatrix
// rows land in distinct banks, conflict-free). hi + lo planes.
#define OB_W1T_H 0
#define OB_W1T_L 9216
#define OB_W2T_H 18432
#define OB_W2T_L 27648
#define OB_W2_H  36864
#define OB_W2_L  46080
#define OB_W1Q_H 55296
#define OB_W1Q_L 59904
#define OB_B1    64512
#define OB_B2    64768
#define OB_W3    65024
#define SMEM_TOTAL 65280

// One GEMM: for each ktp, load B-frags for 4 nt (8 ldm4 back-to-back,
// MLP=8), then run their 12 MMAs. Per-c[nt] order: ktp asc, s asc —
// identical to the reference ordering.
template <int NT>
__device__ __forceinline__ void run_gemm(float (&c)[8][4],
                                         const u32 (&Ah)[4][4],
                                         const u32 (&Al)[4][4],
                                         u32 bh_base, u32 bl_base) {
    #pragma unroll
    for (int nt = 0; nt < NT; nt++)
        #pragma unroll
        for (int q = 0; q < 4; q++) c[nt][q] = 0.0f;

    #pragma unroll
    for (int ktp = 0; ktp < 2; ktp++) {
        #pragma unroll
        for (int ng = 0; ng < NT / 4; ng++) {
            u32 bh[4][4], bl[4][4];
            #pragma unroll
            for (int v = 0; v < 4; v++) {
                const int nt = 4 * ng + v;
                ldm4(bh[v], bh_base + nt * 1152 + ktp * 64);
                ldm4(bl[v], bl_base + nt * 1152 + ktp * 64);
            }
            #pragma unroll
            for (int v = 0; v < 4; v++) {
                const int nt = 4 * ng + v;
                #pragma unroll
                for (int s = 0; s < 2; s++) {
                    const int kt = 2 * ktp + s;
                    MMA(c[nt], Ah[kt], bh[v][2*s], bh[v][2*s+1]);
                    MMA(c[nt], Ah[kt], bl[v][2*s], bl[v][2*s+1]);
                    MMA(c[nt], Al[kt], bh[v][2*s], bh[v][2*s+1]);
                }
            }
        }
    }
}

__global__ void __launch_bounds__(256, 2)
lnn_kernel(const float* __restrict__ X,
           const float* __restrict__ W1g, const float* __restrict__ b1g,
           const float* __restrict__ W2g, const float* __restrict__ b2g,
           const float* __restrict__ W3g,
           float* __restrict__ out, int B)
{
    extern __shared__ char smem[];
    __half* sh = reinterpret_cast<__half*>(smem);
    float* sb1 = reinterpret_cast<float*>(smem + OB_B1);
    float* sb2 = reinterpret_cast<float*>(smem + OB_B2);
    float* sw3 = reinterpret_cast<float*>(smem + OB_W3);

    const int tid = threadIdx.x;
    const int wid = tid >> 5, lane = tid & 31;
    const int g = lane >> 2, tig = lane & 3;

    // ---- one-time weight staging: fp16 hi/lo planes, [n][k] stride 72 ----
    for (int idx = tid; idx < 4096; idx += 256) {
        const int r = idx >> 6, cc = idx & 63;
        {
            const float v = W1g[idx];                         // W1[r][cc]
            const __half hh = __float2half_rn(v);
            const __half hl = __float2half_rn(v - __half2float(hh));
            sh[(OB_W1T_H >> 1) + cc * 72 + r] = hh;           // W1T[n=cc][k=r]
            sh[(OB_W1T_L >> 1) + cc * 72 + r] = hl;
            if (r < 32) {                                     // W1q[n=r][k=cc]
                sh[(OB_W1Q_H >> 1) + r * 72 + cc] = hh;
                sh[(OB_W1Q_L >> 1) + r * 72 + cc] = hl;
            }
        }
        {
            const float v = W2g[idx];                         // W2[r][cc]
            const __half hh = __float2half_rn(v);
            const __half hl = __float2half_rn(v - __half2float(hh));
            sh[(OB_W2T_H >> 1) + cc * 72 + r] = hh;           // W2T[n=cc][k=r]
            sh[(OB_W2T_L >> 1) + cc * 72 + r] = hl;
            sh[(OB_W2_H >> 1) + r * 72 + cc] = hh;            // W2[n=r][k=cc]
            sh[(OB_W2_L >> 1) + r * 72 + cc] = hl;
        }
    }
    if (tid < 64) { sb1[tid] = b1g[tid]; sb2[tid] = b2g[tid]; sw3[tid] = W3g[tid]; }
    __syncthreads();

    const u32 sbase = smem_addr(smem);
    const u32 laneoff = (lane & 7) * 144 + (lane >> 3) * 16;
    const u32 bW1T_h = sbase + OB_W1T_H + laneoff, bW1T_l = sbase + OB_W1T_L + laneoff;
    const u32 bW2T_h = sbase + OB_W2T_H + laneoff, bW2T_l = sbase + OB_W2T_L + laneoff;
    const u32 bW2_h  = sbase + OB_W2_H  + laneoff, bW2_l  = sbase + OB_W2_L  + laneoff;
    const u32 bW1Q_h = sbase + OB_W1Q_H + laneoff, bW1Q_l = sbase + OB_W1Q_L + laneoff;

    const int ntiles = (B + 127) >> 7;          // 128 rows per CTA tile
    float c[8][4];
    u32 Ah[4][4], Al[4][4];

    for (int tile = blockIdx.x; tile < ntiles; tile += gridDim.x) {
        const int rowbase = tile * 128 + wid * 16;

        // ---- A = X fragments straight from gmem (fp32 -> hi/lo fp16) ----
        {
            int r0 = rowbase + g;
            int r1 = r0 + 8;
            if (r0 >= B) r0 = B - 1;
            if (r1 >= B) r1 = B - 1;
            const float* x0 = X + (size_t)r0 * 64 + 2 * tig;
            const float* x1 = X + (size_t)r1 * 64 + 2 * tig;
            #pragma unroll
            for (int kt = 0; kt < 4; kt++) {
                const float2 v00 = *reinterpret_cast<const float2*>(x0 + 16*kt);
                const float2 v01 = *reinterpret_cast<const float2*>(x0 + 16*kt + 8);
                const float2 v10 = *reinterpret_cast<const float2*>(x1 + 16*kt);
                const float2 v11 = *reinterpret_cast<const float2*>(x1 + 16*kt + 8);
                split2(v00.x, v00.y, Ah[kt][0], Al[kt][0]);
                split2(v10.x, v10.y, Ah[kt][1], Al[kt][1]);
                split2(v01.x, v01.y, Ah[kt][2], Al[kt][2]);
                split2(v11.x, v11.y, Ah[kt][3], Al[kt][3]);
            }
        }

        // ================= GEMM1: PRE1 = X @ W1 =================
        run_gemm<8>(c, Ah, Al, bW1T_h, bW1T_l);
        u32 m1 = 0u;
        #pragma unroll
        for (int nt = 0; nt < 8; nt++) {
            const float2 bv = *reinterpret_cast<const float2*>(sb1 + 8*nt + 2*tig);
            float p0 = c[nt][0] + bv.x;
            float p1 = c[nt][1] + bv.y;
            float p2 = c[nt][2] + bv.x;
            float p3 = c[nt][3] + bv.y;
            if (p0 > 0.0f) m1 |= 1u << (4*nt + 0); else p0 = 0.0f;
            if (p1 > 0.0f) m1 |= 1u << (4*nt + 1); else p1 = 0.0f;
            if (p2 > 0.0f) m1 |= 1u << (4*nt + 2); else p2 = 0.0f;
            if (p3 > 0.0f) m1 |= 1u << (4*nt + 3); else p3 = 0.0f;
            const int kt = nt >> 1, o = (nt & 1) << 1;
            split2(p0, p1, Ah[kt][o],     Al[kt][o]);
            split2(p2, p3, Ah[kt][o + 1], Al[kt][o + 1]);
        }

        // ================= GEMM2: PRE2 = H @ W2 =================
        run_gemm<8>(c, Ah, Al, bW2T_h, bW2T_l);
        #pragma unroll
        for (int nt = 0; nt < 8; nt++) {
            const float2 bv = *reinterpret_cast<const float2*>(sb2 + 8*nt + 2*tig);
            const float2 wv = *reinterpret_cast<const float2*>(sw3 + 8*nt + 2*tig);
            const float d0 = (c[nt][0] + bv.x > 0.0f) ? wv.x : 0.0f;
            const float d1 = (c[nt][1] + bv.y > 0.0f) ? wv.y : 0.0f;
            const float d2 = (c[nt][2] + bv.x > 0.0f) ? wv.x : 0.0f;
            const float d3 = (c[nt][3] + bv.y > 0.0f) ? wv.y : 0.0f;
            const int kt = nt >> 1, o = (nt & 1) << 1;
            split2(d0, d1, Ah[kt][o],     Al[kt][o]);
            split2(d2, d3, Ah[kt][o + 1], Al[kt][o + 1]);
        }

        // ================= GEMM3: T = D2 @ W2^T =================
        run_gemm<8>(c, Ah, Al, bW2_h, bW2_l);
        #pragma unroll
        for (int nt = 0; nt < 8; nt++) {
            const float t0 = ((m1 >> (4*nt + 0)) & 1u) ? -c[nt][0] : 0.0f;
            const float t1 = ((m1 >> (4*nt + 1)) & 1u) ? -c[nt][1] : 0.0f;
            const float t2 = ((m1 >> (4*nt + 2)) & 1u) ? -c[nt][2] : 0.0f;
            const float t3 = ((m1 >> (4*nt + 3)) & 1u) ? -c[nt][3] : 0.0f;
            const int kt = nt >> 1, o = (nt & 1) << 1;
            split2(t0, t1, Ah[kt][o],     Al[kt][o]);
            split2(t2, t3, Ah[kt][o + 1], Al[kt][o + 1]);
        }

        // ============ GEMM4: OUT = D1 @ W1q^T (N = 32) ============
        run_gemm<4>(c, Ah, Al, bW1Q_h, bW1Q_l);
        {
            const int r0 = rowbase + g;
            const int r1 = r0 + 8;
            #pragma unroll
            for (int nt = 0; nt < 4; nt++) {
                const int col = 8 * nt + 2 * tig;
                if (r0 < B)
                    *reinterpret_cast<float2*>(out + (size_t)r0 * 32 + col) =
                        make_float2(c[nt][0], c[nt][1]);
                if (r1 < B)
                    *reinterpret_cast<float2*>(out + (size_t)r1 * 32 + col) =
                        make_float2(c[nt][2], c[nt][3]);
            }
        }
    }
}

extern "C" void kernel_launch(void* const* d_in, const int* in_sizes, int n_in,
                              void* d_out, int out_size)
{
    const float* X  = (const float*)d_in[0];
    const float* W1 = (const float*)d_in[1];
    const float* b1 = (const float*)d_in[2];
    const float* W2 = (const float*)d_in[3];
    const float* b2 = (const float*)d_in[4];
    const float* W3 = (const float*)d_in[5];
    float* out = (float*)d_out;

    const int B = in_sizes[0] / 64;
    const int ntiles = (B + 127) / 128;
    int grid = 148 * 2;                 // persistent, 2 CTAs/SM (16 warps/SM)
    if (grid > ntiles) grid = ntiles;

    cudaFuncSetAttribute(lnn_kernel,
                         cudaFuncAttributeMaxDynamicSharedMemorySize,
                         SMEM_TOTAL);
    lnn_kernel<<<grid, 256, SMEM_TOTAL>>>(X, W1, b1, W2, b2, W3, out, B);
}

// round 10
// speedup vs baseline: 1.0444x; 1.0444x over previous
#include <cuda_runtime.h>
#include <cuda_fp16.h>
#include <cstdint>

// LNN Euler-Lagrange residual: ReLU MLP => grad-of-grad vanishes under
// autodiff; output is exactly -dL/dq.
//
// mma.sync.m16n8k16 chain, 4 GEMMs with register-only glue (C-frag layout
// == A-frag layout). fp16 hi/lo split (3 products). R10: two sample-tiles
// per warp, software-pipelined so each tile's GEMM chunks interleave with
// the OTHER tile's epilogue chunks -> tensor pipe stays fed through
// epilogues. W3 folded into GEMM3's B operand (V = W2 * diag(W3)) so
// GEMM3's A is the exact {0,1} mask: 8 MMAs/chunk instead of 12.

typedef uint32_t u32;

__device__ __forceinline__ u32 smem_addr(const void* p) {
    u32 a;
    asm("{ .reg .u64 t; cvta.to.shared.u64 t, %1; cvt.u32.u64 %0, t; }"
        : "=r"(a) : "l"(p));
    return a;
}
__device__ __forceinline__ u32 pack_f16x2(float x0, float x1) {   // lo=x0, hi=x1
    u32 r; asm("cvt.rn.f16x2.f32 %0, %1, %2;" : "=r"(r) : "f"(x1), "f"(x0));
    return r;
}
__device__ __forceinline__ float2 unpack_h2(u32 v) {
    float2 r;
    asm("{ .reg .b16 lo1, hi1; mov.b32 {lo1, hi1}, %2; "
        "cvt.f32.f16 %0, lo1; cvt.f32.f16 %1, hi1; }"
        : "=f"(r.x), "=f"(r.y) : "r"(v));
    return r;
}
__device__ __forceinline__ void split2(float x0, float x1, u32& hi, u32& lo) {
    hi = pack_f16x2(x0, x1);
    const float2 hf = unpack_h2(hi);
    lo = pack_f16x2(x0 - hf.x, x1 - hf.y);
}
__device__ __forceinline__ void ldm4(u32 r[4], u32 addr) {
    asm volatile("ldmatrix.sync.aligned.m8n8.x4.shared.b16 {%0,%1,%2,%3}, [%4];"
                 : "=r"(r[0]), "=r"(r[1]), "=r"(r[2]), "=r"(r[3]) : "r"(addr));
}
#define MMA(cc, aa, b0, b1)                                                  \
    asm volatile("mma.sync.aligned.m16n8k16.row.col.f32.f16.f16.f32 "        \
        "{%0,%1,%2,%3}, {%4,%5,%6,%7}, {%8,%9}, {%0,%1,%2,%3};"              \
        : "+f"((cc)[0]), "+f"((cc)[1]), "+f"((cc)[2]), "+f"((cc)[3])         \
        : "r"((aa)[0]), "r"((aa)[1]), "r"((aa)[2]), "r"((aa)[3]),            \
          "r"(b0), "r"(b1))

// smem: weight tiles [n][k] fp16, row stride 72 halfs (144 B, conflict-free
// ldmatrix). hi + lo planes. V = W2 * diag(W3) for GEMM3.
#define OB_W1T_H 0
#define OB_W1T_L 9216
#define OB_W2T_H 18432
#define OB_W2T_L 27648
#define OB_V_H   36864
#define OB_V_L   46080
#define OB_W1Q_H 55296
#define OB_W1Q_L 59904
#define OB_B1    64512
#define OB_B2    64768
#define SMEM_TOTAL 65024

// ---- GEMM chunk: one nt (8 output cols), all K. 3-product version. ----
#define G_CHUNK3(c, Ah, Al, BH, BL, nt) do {                                 \
    (c)[nt][0] = 0.0f; (c)[nt][1] = 0.0f; (c)[nt][2] = 0.0f; (c)[nt][3] = 0.0f; \
    u32 b0h[4], b0l[4], b1h[4], b1l[4];                                      \
    ldm4(b0h, (BH) + (nt) * 1152);                                           \
    ldm4(b0l, (BL) + (nt) * 1152);                                           \
    ldm4(b1h, (BH) + (nt) * 1152 + 64);                                      \
    ldm4(b1l, (BL) + (nt) * 1152 + 64);                                      \
    MMA((c)[nt], (Ah)[0], b0h[0], b0h[1]);                                   \
    MMA((c)[nt], (Ah)[0], b0l[0], b0l[1]);                                   \
    MMA((c)[nt], (Al)[0], b0h[0], b0h[1]);                                   \
    MMA((c)[nt], (Ah)[1], b0h[2], b0h[3]);                                   \
    MMA((c)[nt], (Ah)[1], b0l[2], b0l[3]);                                   \
    MMA((c)[nt], (Al)[1], b0h[2], b0h[3]);                                   \
    MMA((c)[nt], (Ah)[2], b1h[0], b1h[1]);                                   \
    MMA((c)[nt], (Ah)[2], b1l[0], b1l[1]);                                   \
    MMA((c)[nt], (Al)[2], b1h[0], b1h[1]);                                   \
    MMA((c)[nt], (Ah)[3], b1h[2], b1h[3]);                                   \
    MMA((c)[nt], (Ah)[3], b1l[2], b1l[3]);                                   \
    MMA((c)[nt], (Al)[3], b1h[2], b1h[3]);                                   \
} while (0)

// ---- 2-product version (A exact in fp16 -> no A residual term). ----
#define G_CHUNK2(c, Ah, BH, BL, nt) do {                                     \
    (c)[nt][0] = 0.0f; (c)[nt][1] = 0.0f; (c)[nt][2] = 0.0f; (c)[nt][3] = 0.0f; \
    u32 b0h[4], b0l[4], b1h[4], b1l[4];                                      \
    ldm4(b0h, (BH) + (nt) * 1152);                                           \
    ldm4(b0l, (BL) + (nt) * 1152);                                           \
    ldm4(b1h, (BH) + (nt) * 1152 + 64);                                      \
    ldm4(b1l, (BL) + (nt) * 1152 + 64);                                      \
    MMA((c)[nt], (Ah)[0], b0h[0], b0h[1]);                                   \
    MMA((c)[nt], (Ah)[0], b0l[0], b0l[1]);                                   \
    MMA((c)[nt], (Ah)[1], b0h[2], b0h[3]);                                   \
    MMA((c)[nt], (Ah)[1], b0l[2], b0l[3]);                                   \
    MMA((c)[nt], (Ah)[2], b1h[0], b1h[1]);                                   \
    MMA((c)[nt], (Ah)[2], b1l[0], b1l[1]);                                   \
    MMA((c)[nt], (Ah)[3], b1h[2], b1h[3]);                                   \
    MMA((c)[nt], (Ah)[3], b1l[2], b1l[3]);                                   \
} while (0)

// ---- epilogue chunks (one nt each) ----
#define EPI1_CHUNK(c, Ah, Al, m1, nt) do {                                   \
    const float2 bv = *reinterpret_cast<const float2*>(sb1 + 8*(nt) + 2*tig);\
    float p0 = (c)[nt][0] + bv.x;                                            \
    float p1 = (c)[nt][1] + bv.y;                                            \
    float p2 = (c)[nt][2] + bv.x;                                            \
    float p3 = (c)[nt][3] + bv.y;                                            \
    if (p0 > 0.0f) m1 |= 1u << (4*(nt)+0); else p0 = 0.0f;                   \
    if (p1 > 0.0f) m1 |= 1u << (4*(nt)+1); else p1 = 0.0f;                   \
    if (p2 > 0.0f) m1 |= 1u << (4*(nt)+2); else p2 = 0.0f;                   \
    if (p3 > 0.0f) m1 |= 1u << (4*(nt)+3); else p3 = 0.0f;                   \
    const int kt = (nt) >> 1, o = ((nt) & 1) << 1;                           \
    split2(p0, p1, (Ah)[kt][o],     (Al)[kt][o]);                            \
    split2(p2, p3, (Ah)[kt][o + 1], (Al)[kt][o + 1]);                        \
} while (0)

#define EPI2_CHUNK(c, Ah, nt) do {                                           \
    const float2 bv = *reinterpret_cast<const float2*>(sb2 + 8*(nt) + 2*tig);\
    const float d0 = ((c)[nt][0] + bv.x > 0.0f) ? 1.0f : 0.0f;               \
    const float d1 = ((c)[nt][1] + bv.y > 0.0f) ? 1.0f : 0.0f;               \
    const float d2 = ((c)[nt][2] + bv.x > 0.0f) ? 1.0f : 0.0f;               \
    const float d3 = ((c)[nt][3] + bv.y > 0.0f) ? 1.0f : 0.0f;               \
    const int kt = (nt) >> 1, o = ((nt) & 1) << 1;                           \
    (Ah)[kt][o]     = pack_f16x2(d0, d1);                                    \
    (Ah)[kt][o + 1] = pack_f16x2(d2, d3);                                    \
} while (0)

#define EPI3_CHUNK(c, Ah, Al, m1, nt) do {                                   \
    const float t0 = ((m1 >> (4*(nt)+0)) & 1u) ? -(c)[nt][0] : 0.0f;         \
    const float t1 = ((m1 >> (4*(nt)+1)) & 1u) ? -(c)[nt][1] : 0.0f;         \
    const float t2 = ((m1 >> (4*(nt)+2)) & 1u) ? -(c)[nt][2] : 0.0f;         \
    const float t3 = ((m1 >> (4*(nt)+3)) & 1u) ? -(c)[nt][3] : 0.0f;         \
    const int kt = (nt) >> 1, o = ((nt) & 1) << 1;                           \
    split2(t0, t1, (Ah)[kt][o],     (Al)[kt][o]);                            \
    split2(t2, t3, (Ah)[kt][o + 1], (Al)[kt][o + 1]);                        \
} while (0)

#define STORE_CHUNK(c, r0v, r1v, nt) do {                                    \
    const int col = 8*(nt) + 2*tig;                                          \
    if ((r0v) < B)                                                           \
        *reinterpret_cast<float2*>(out + (size_t)(r0v)*32 + col) =           \
            make_float2((c)[nt][0], (c)[nt][1]);                             \
    if ((r1v) < B)                                                           \
        *reinterpret_cast<float2*>(out + (size_t)(r1v)*32 + col) =           \
            make_float2((c)[nt][2], (c)[nt][3]);                             \
} while (0)

#define LOAD_A(rowbase, Ah, Al) do {                                         \
    int r0 = (rowbase) + g;                                                  \
    int r1 = r0 + 8;                                                         \
    if (r0 >= B) r0 = B - 1;                                                 \
    if (r1 >= B) r1 = B - 1;                                                 \
    const float* x0 = X + (size_t)r0 * 64 + 2 * tig;                         \
    const float* x1 = X + (size_t)r1 * 64 + 2 * tig;                         \
    _Pragma("unroll")                                                        \
    for (int kt = 0; kt < 4; kt++) {                                         \
        const float2 v00 = *reinterpret_cast<const float2*>(x0 + 16*kt);     \
        const float2 v01 = *reinterpret_cast<const float2*>(x0 + 16*kt + 8); \
        const float2 v10 = *reinterpret_cast<const float2*>(x1 + 16*kt);     \
        const float2 v11 = *reinterpret_cast<const float2*>(x1 + 16*kt + 8); \
        split2(v00.x, v00.y, (Ah)[kt][0], (Al)[kt][0]);                      \
        split2(v10.x, v10.y, (Ah)[kt][1], (Al)[kt][1]);                      \
        split2(v01.x, v01.y, (Ah)[kt][2], (Al)[kt][2]);                      \
        split2(v11.x, v11.y, (Ah)[kt][3], (Al)[kt][3]);                      \
    }                                                                        \
} while (0)

__global__ void __launch_bounds__(128, 2)
lnn_kernel(const float* __restrict__ X,
           const float* __restrict__ W1g, const float* __restrict__ b1g,
           const float* __restrict__ W2g, const float* __restrict__ b2g,
           const float* __restrict__ W3g,
           float* __restrict__ out, int B)
{
    extern __shared__ char smem[];
    __half* sh = reinterpret_cast<__half*>(smem);
    float* sb1 = reinterpret_cast<float*>(smem + OB_B1);
    float* sb2 = reinterpret_cast<float*>(smem + OB_B2);

    const int tid = threadIdx.x;
    const int wid = tid >> 5, lane = tid & 31;
    const int g = lane >> 2, tig = lane & 3;

    // ---- one-time weight staging: fp16 hi/lo planes, [n][k] stride 72 ----
    for (int idx = tid; idx < 4096; idx += 128) {
        const int r = idx >> 6, cc = idx & 63;
        {
            const float v = W1g[idx];                         // W1[r][cc]
            const __half hh = __float2half_rn(v);
            const __half hl = __float2half_rn(v - __half2float(hh));
            sh[(OB_W1T_H >> 1) + cc * 72 + r] = hh;           // W1T[n=cc][k=r]
            sh[(OB_W1T_L >> 1) + cc * 72 + r] = hl;
            if (r < 32) {                                     // W1q[n=r][k=cc]
                sh[(OB_W1Q_H >> 1) + r * 72 + cc] = hh;
                sh[(OB_W1Q_L >> 1) + r * 72 + cc] = hl;
            }
        }
        {
            const float v = W2g[idx];                         // W2[r][cc]
            const __half hh = __float2half_rn(v);
            const __half hl = __float2half_rn(v - __half2float(hh));
            sh[(OB_W2T_H >> 1) + cc * 72 + r] = hh;           // W2T[n=cc][k=r]
            sh[(OB_W2T_L >> 1) + cc * 72 + r] = hl;
            const float vv = v * W3g[cc];                     // V[n=r][k=cc]
            const __half vh = __float2half_rn(vv);
            const __half vl = __float2half_rn(vv - __half2float(vh));
            sh[(OB_V_H >> 1) + r * 72 + cc] = vh;
            sh[(OB_V_L >> 1) + r * 72 + cc] = vl;
        }
    }
    if (tid < 64) { sb1[tid] = b1g[tid]; sb2[tid] = b2g[tid]; }
    __syncthreads();

    const u32 sbase = smem_addr(smem);
    const u32 laneoff = (lane & 7) * 144 + (lane >> 3) * 16;
    const u32 bW1T_h = sbase + OB_W1T_H + laneoff, bW1T_l = sbase + OB_W1T_L + laneoff;
    const u32 bW2T_h = sbase + OB_W2T_H + laneoff, bW2T_l = sbase + OB_W2T_L + laneoff;
    const u32 bV_h   = sbase + OB_V_H   + laneoff, bV_l   = sbase + OB_V_L   + laneoff;
    const u32 bW1Q_h = sbase + OB_W1Q_H + laneoff, bW1Q_l = sbase + OB_W1Q_L + laneoff;

    const int ntiles = (B + 127) >> 7;          // 128 rows per CTA tile
    float c0[8][4], c1[8][4];
    u32 Ah0[4][4], Al0[4][4], Ah1[4][4], Al1[4][4];

    for (int tile = blockIdx.x; tile < ntiles; tile += gridDim.x) {
        const int rb0 = tile * 128 + wid * 16;   // tile T0 (rows 0-63 of CTA)
        const int rb1 = rb0 + 64;                // tile T1 (rows 64-127)
        u32 m1_0 = 0u, m1_1 = 0u;

        LOAD_A(rb0, Ah0, Al0);
        LOAD_A(rb1, Ah1, Al1);

        // GEMM1(T0)
        #pragma unroll
        for (int nt = 0; nt < 8; nt++)
            G_CHUNK3(c0, Ah0, Al0, bW1T_h, bW1T_l, nt);

        // GEMM1(T1) interleaved with epi1(T0)
        #pragma unroll
        for (int nt = 0; nt < 8; nt++) {
            G_CHUNK3(c1, Ah1, Al1, bW1T_h, bW1T_l, nt);
            EPI1_CHUNK(c0, Ah0, Al0, m1_0, nt);
        }

        // GEMM2(T0) interleaved with epi1(T1)
        #pragma unroll
        for (int nt = 0; nt < 8; nt++) {
            G_CHUNK3(c0, Ah0, Al0, bW2T_h, bW2T_l, nt);
            EPI1_CHUNK(c1, Ah1, Al1, m1_1, nt);
        }

        // GEMM2(T1) interleaved with epi2(T0)
        #pragma unroll
        for (int nt = 0; nt < 8; nt++) {
            G_CHUNK3(c1, Ah1, Al1, bW2T_h, bW2T_l, nt);
            EPI2_CHUNK(c0, Ah0, nt);
        }

        // GEMM3(T0) interleaved with epi2(T1)  (A exact -> 2-product chunks)
        #pragma unroll
        for (int nt = 0; nt < 8; nt++) {
            G_CHUNK2(c0, Ah0, bV_h, bV_l, nt);
            EPI2_CHUNK(c1, Ah1, nt);
        }

        // GEMM3(T1) interleaved with epi3(T0)
        #pragma unroll
        for (int nt = 0; nt < 8; nt++) {
            G_CHUNK2(c1, Ah1, bV_h, bV_l, nt);
            EPI3_CHUNK(c0, Ah0, Al0, m1_0, nt);
        }

        // GEMM4(T0) (N=32: 4 chunks) interleaved with epi3(T1) (8 chunks)
        #pragma unroll
        for (int nt = 0; nt < 4; nt++) {
            G_CHUNK3(c0, Ah0, Al0, bW1Q_h, bW1Q_l, nt);
            EPI3_CHUNK(c1, Ah1, Al1, m1_1, 2*nt);
            EPI3_CHUNK(c1, Ah1, Al1, m1_1, 2*nt + 1);
        }

        // GEMM4(T1) interleaved with store(T0)
        {
            const int r0 = rb0 + g, r1 = r0 + 8;
            #pragma unroll
            for (int nt = 0; nt < 4; nt++) {
                G_CHUNK3(c1, Ah1, Al1, bW1Q_h, bW1Q_l, nt);
                STORE_CHUNK(c0, r0, r1, nt);
            }
        }

        // store(T1)
        {
            const int r0 = rb1 + g, r1 = r0 + 8;
            #pragma unroll
            for (int nt = 0; nt < 4; nt++)
                STORE_CHUNK(c1, r0, r1, nt);
        }
    }
}

extern "C" void kernel_launch(void* const* d_in, const int* in_sizes, int n_in,
                              void* d_out, int out_size)
{
    const float* X  = (const float*)d_in[0];
    const float* W1 = (const float*)d_in[1];
    const float* b1 = (const float*)d_in[2];
    const float* W2 = (const float*)d_in[3];
    const float* b2 = (const float*)d_in[4];
    const float* W3 = (const float*)d_in[5];
    float* out = (float*)d_out;

    const int B = in_sizes[0] / 64;
    const int ntiles = (B + 127) / 128;
    int grid = 148 * 2;                 // persistent, 2 CTAs/SM
    if (grid > ntiles) grid = ntiles;

    cudaFuncSetAttribute(lnn_kernel,
                         cudaFuncAttributeMaxDynamicSharedMemorySize,
                         SMEM_TOTAL);
    lnn_kernel<<<grid, 128, SMEM_TOTAL>>>(X, W1, b1, W2, b2, W3, out, B);
}